// round 4
// baseline (speedup 1.0000x reference)
#include <cuda_runtime.h>

// GCN: 2x gcn_conv + concat + leaky_relu + linear head.
// N=100000 nodes, E=600000 edges, D=128.
// edge_index is read as int32 (harness dtype), with a runtime probe fallback to int64.

#define NMAX 100352
#define EMAX 602112

// ---- static device scratch (~106 MB total, 16B aligned) ----
__device__ __align__(16) float g_h  [(size_t)NMAX * 128];  // GEMM output (h1 then h2)
__device__ __align__(16) float g_agg[(size_t)NMAX * 128];  // lk(agg1 + b1)
__device__ __align__(16) float g_dinv[NMAX];
__device__ __align__(16) int   g_deg [NMAX];     // in-degree (edges only)
__device__ __align__(16) int   g_rowptr[NMAX];   // exclusive prefix sum
__device__ __align__(16) int   g_cursor[NMAX];   // placement cursors
__device__ __align__(16) int   g_csrc[EMAX];     // edge sources grouped by dst
__device__ __align__(16) int   g_bsum[1024];     // scan block partials
__device__ int g_is64;                           // 1 if edge_index is int64

__device__ __forceinline__ float lk(float v) { return v > 0.f ? v : 0.01f * v; }

__device__ __forceinline__ int edge_at(const int* ei, int is64, size_t idx) {
    if (is64) return (int)((const long long*)ei)[idx];
    return ei[idx];
}

// ---------------- dtype probe ----------------
// int64 values in [0, N) have zero high words at odd int32 positions.
__global__ void k_probe(const int* __restrict__ ei) {
    int allz = 1;
    for (int t = 0; t < 64; t++)
        if (ei[2 * t + 1] != 0) { allz = 0; break; }
    g_is64 = allz;
}

// ---------------- CSR build ----------------
__global__ void k_zero_deg(int n) {
    int i = blockIdx.x * blockDim.x + threadIdx.x;
    if (i < n) g_deg[i] = 0;
}

__global__ void k_hist(const int* __restrict__ ei, int E) {
    int e = blockIdx.x * blockDim.x + threadIdx.x;
    if (e < E) {
        int d = edge_at(ei, g_is64, (size_t)E + e);
        atomicAdd(&g_deg[d], 1);
    }
}

__global__ void __launch_bounds__(1024) k_scan1(int n) {
    __shared__ int sh[1024];
    int tid = threadIdx.x;
    int i = blockIdx.x * 1024 + tid;
    int v = (i < n) ? g_deg[i] : 0;
    sh[tid] = v;
    __syncthreads();
    for (int o = 1; o < 1024; o <<= 1) {
        int t = (tid >= o) ? sh[tid - o] : 0;
        __syncthreads();
        sh[tid] += t;
        __syncthreads();
    }
    if (i < n) g_rowptr[i] = sh[tid] - v;   // exclusive
    if (tid == 1023) g_bsum[blockIdx.x] = sh[1023];
}

__global__ void __launch_bounds__(1024) k_scan2(int nb) {
    __shared__ int sh[1024];
    int tid = threadIdx.x;
    int v = (tid < nb) ? g_bsum[tid] : 0;
    sh[tid] = v;
    __syncthreads();
    for (int o = 1; o < 1024; o <<= 1) {
        int t = (tid >= o) ? sh[tid - o] : 0;
        __syncthreads();
        sh[tid] += t;
        __syncthreads();
    }
    if (tid < nb) g_bsum[tid] = sh[tid] - v;
}

__global__ void k_scan3(int n) {
    int i = blockIdx.x * blockDim.x + threadIdx.x;
    if (i >= n) return;
    int r = g_rowptr[i] + g_bsum[i >> 10];
    g_rowptr[i] = r;
    g_cursor[i] = r;
    g_dinv[i]   = rsqrtf((float)(g_deg[i] + 1));
}

__global__ void k_place(const int* __restrict__ ei, int E) {
    int e = blockIdx.x * blockDim.x + threadIdx.x;
    if (e >= E) return;
    int is64 = g_is64;
    int s = edge_at(ei, is64, e);
    int d = edge_at(ei, is64, (size_t)E + e);
    int pos = atomicAdd(&g_cursor[d], 1);
    g_csrc[pos] = s;
}

// ---------------- SGEMM 1: g_h[M,128] = x[M,128] @ W1[128,128] ----------------
__global__ void __launch_bounds__(256)
k_sgemm1(const float* __restrict__ A, const float* __restrict__ B, int M) {
    __shared__ float As[16][128];   // transposed: As[k][m]
    __shared__ float Bs[16][128];

    int tid = threadIdx.x;
    int m0  = blockIdx.x * 128;
    int ty  = tid >> 4, tx = tid & 15;

    float acc[8][8];
#pragma unroll
    for (int i = 0; i < 8; i++)
#pragma unroll
        for (int j = 0; j < 8; j++) acc[i][j] = 0.f;

    for (int k0 = 0; k0 < 128; k0 += 16) {
#pragma unroll
        for (int i = 0; i < 2; i++) {
            int idx = tid + i * 256;
            int row = idx >> 2;
            int kc  = (idx & 3) << 2;
            float4 v = make_float4(0.f, 0.f, 0.f, 0.f);
            int gr = m0 + row;
            if (gr < M) v = *(const float4*)(A + (size_t)gr * 128 + k0 + kc);
            As[kc + 0][row] = v.x; As[kc + 1][row] = v.y;
            As[kc + 2][row] = v.z; As[kc + 3][row] = v.w;
        }
#pragma unroll
        for (int i = 0; i < 2; i++) {
            int idx = tid + i * 256;
            int row = idx >> 5;
            int c   = (idx & 31) << 2;
            *(float4*)&Bs[row][c] = *(const float4*)(B + (size_t)(k0 + row) * 128 + c);
        }
        __syncthreads();

#pragma unroll
        for (int kk = 0; kk < 16; kk++) {
            float a[8], b[8];
            *(float4*)&a[0] = *(const float4*)&As[kk][ty * 8];
            *(float4*)&a[4] = *(const float4*)&As[kk][ty * 8 + 4];
            *(float4*)&b[0] = *(const float4*)&Bs[kk][tx * 8];
            *(float4*)&b[4] = *(const float4*)&Bs[kk][tx * 8 + 4];
#pragma unroll
            for (int i = 0; i < 8; i++)
#pragma unroll
                for (int j = 0; j < 8; j++)
                    acc[i][j] = fmaf(a[i], b[j], acc[i][j]);
        }
        __syncthreads();
    }

#pragma unroll
    for (int i = 0; i < 8; i++) {
        int gr = m0 + ty * 8 + i;
        if (gr < M) {
            *(float4*)(g_h + (size_t)gr * 128 + tx * 8)     =
                make_float4(acc[i][0], acc[i][1], acc[i][2], acc[i][3]);
            *(float4*)(g_h + (size_t)gr * 128 + tx * 8 + 4) =
                make_float4(acc[i][4], acc[i][5], acc[i][6], acc[i][7]);
        }
    }
}

// ------- SGEMM 2 (dual source): g_h = lk(x)@W2[0:128] + g_agg@W2[128:256] -------
__global__ void __launch_bounds__(256)
k_sgemm2(const float* __restrict__ X, const float* __restrict__ W2, int M) {
    __shared__ float As[16][128];
    __shared__ float Bs[16][128];

    int tid = threadIdx.x;
    int m0  = blockIdx.x * 128;
    int ty  = tid >> 4, tx = tid & 15;

    float acc[8][8];
#pragma unroll
    for (int i = 0; i < 8; i++)
#pragma unroll
        for (int j = 0; j < 8; j++) acc[i][j] = 0.f;

    for (int phase = 0; phase < 2; phase++) {
        const float* A = phase ? g_agg : X;      // g_agg already leaky'd
        const float* B = W2 + (size_t)phase * 128 * 128;
        bool applyLk = (phase == 0);

        for (int k0 = 0; k0 < 128; k0 += 16) {
#pragma unroll
            for (int i = 0; i < 2; i++) {
                int idx = tid + i * 256;
                int row = idx >> 2;
                int kc  = (idx & 3) << 2;
                float4 v = make_float4(0.f, 0.f, 0.f, 0.f);
                int gr = m0 + row;
                if (gr < M) v = *(const float4*)(A + (size_t)gr * 128 + k0 + kc);
                if (applyLk) { v.x = lk(v.x); v.y = lk(v.y); v.z = lk(v.z); v.w = lk(v.w); }
                As[kc + 0][row] = v.x; As[kc + 1][row] = v.y;
                As[kc + 2][row] = v.z; As[kc + 3][row] = v.w;
            }
#pragma unroll
            for (int i = 0; i < 2; i++) {
                int idx = tid + i * 256;
                int row = idx >> 5;
                int c   = (idx & 31) << 2;
                *(float4*)&Bs[row][c] = *(const float4*)(B + (size_t)(k0 + row) * 128 + c);
            }
            __syncthreads();

#pragma unroll
            for (int kk = 0; kk < 16; kk++) {
                float a[8], b[8];
                *(float4*)&a[0] = *(const float4*)&As[kk][ty * 8];
                *(float4*)&a[4] = *(const float4*)&As[kk][ty * 8 + 4];
                *(float4*)&b[0] = *(const float4*)&Bs[kk][tx * 8];
                *(float4*)&b[4] = *(const float4*)&Bs[kk][tx * 8 + 4];
#pragma unroll
                for (int i = 0; i < 8; i++)
#pragma unroll
                    for (int j = 0; j < 8; j++)
                        acc[i][j] = fmaf(a[i], b[j], acc[i][j]);
            }
            __syncthreads();
        }
    }

#pragma unroll
    for (int i = 0; i < 8; i++) {
        int gr = m0 + ty * 8 + i;
        if (gr < M) {
            *(float4*)(g_h + (size_t)gr * 128 + tx * 8)     =
                make_float4(acc[i][0], acc[i][1], acc[i][2], acc[i][3]);
            *(float4*)(g_h + (size_t)gr * 128 + tx * 8 + 4) =
                make_float4(acc[i][4], acc[i][5], acc[i][6], acc[i][7]);
        }
    }
}

// ------- layer-1 aggregation (warp per node): g_agg[v] = lk(agg1[v] + b1) -------
__global__ void k_gather1(const float* __restrict__ b1, int N) {
    int node = (blockIdx.x * blockDim.x + threadIdx.x) >> 5;
    int lane = threadIdx.x & 31;
    if (node >= N) return;
    int c4 = lane << 2;
    float di = g_dinv[node];

    float4 acc = *(const float4*)(g_h + (size_t)node * 128 + c4);  // self-loop
    float s = di * di;
    acc.x *= s; acc.y *= s; acc.z *= s; acc.w *= s;

    int start = g_rowptr[node];
    int deg   = g_deg[node];
    for (int j = 0; j < deg; j++) {
        int src = g_csrc[start + j];
        float nrm = di * g_dinv[src];
        float4 v = *(const float4*)(g_h + (size_t)src * 128 + c4);
        acc.x = fmaf(v.x, nrm, acc.x); acc.y = fmaf(v.y, nrm, acc.y);
        acc.z = fmaf(v.z, nrm, acc.z); acc.w = fmaf(v.w, nrm, acc.w);
    }
    float4 bb = *(const float4*)(b1 + c4);
    acc.x = lk(acc.x + bb.x); acc.y = lk(acc.y + bb.y);
    acc.z = lk(acc.z + bb.z); acc.w = lk(acc.w + bb.w);
    *(float4*)(g_agg + (size_t)node * 128 + c4) = acc;
}

// ------- layer-2 aggregation fused with head: out[v] = lk(agg2+b2).Wout + bout -------
__global__ void k_gather2(const float* __restrict__ b2, const float* __restrict__ Wout,
                          const float* __restrict__ bout, float* __restrict__ out, int N) {
    int node = (blockIdx.x * blockDim.x + threadIdx.x) >> 5;
    int lane = threadIdx.x & 31;
    if (node >= N) return;
    int c4 = lane << 2;
    float di = g_dinv[node];

    float4 acc = *(const float4*)(g_h + (size_t)node * 128 + c4);
    float s = di * di;
    acc.x *= s; acc.y *= s; acc.z *= s; acc.w *= s;

    int start = g_rowptr[node];
    int deg   = g_deg[node];
    for (int j = 0; j < deg; j++) {
        int src = g_csrc[start + j];
        float nrm = di * g_dinv[src];
        float4 v = *(const float4*)(g_h + (size_t)src * 128 + c4);
        acc.x = fmaf(v.x, nrm, acc.x); acc.y = fmaf(v.y, nrm, acc.y);
        acc.z = fmaf(v.z, nrm, acc.z); acc.w = fmaf(v.w, nrm, acc.w);
    }
    float4 bb = *(const float4*)(b2 + c4);
    float4 ww = *(const float4*)(Wout + c4);
    float r = lk(acc.x + bb.x) * ww.x + lk(acc.y + bb.y) * ww.y +
              lk(acc.z + bb.z) * ww.z + lk(acc.w + bb.w) * ww.w;
#pragma unroll
    for (int o = 16; o; o >>= 1) r += __shfl_xor_sync(0xFFFFFFFFu, r, o);
    if (lane == 0) out[node] = r + bout[0];
}

// ---------------- launch ----------------
extern "C" void kernel_launch(void* const* d_in, const int* in_sizes, int n_in,
                              void* d_out, int out_size) {
    const float* x    = (const float*)d_in[0];
    const int*   ei   = (const int*)d_in[1];     // int32 edge_index (probed for int64)
    const float* W1   = (const float*)d_in[2];
    const float* b1   = (const float*)d_in[3];
    const float* W2   = (const float*)d_in[4];
    const float* b2   = (const float*)d_in[5];
    const float* Wout = (const float*)d_in[6];
    const float* bout = (const float*)d_in[7];
    float*       out  = (float*)d_out;

    int N = in_sizes[0] / 128;
    int E = in_sizes[1] / 2;

    const int T = 256;
    int gN = (N + T - 1) / T;
    int gE = (E + T - 1) / T;
    int gW = (N * 32 + T - 1) / T;     // warp-per-node kernels
    int gM = (N + 127) / 128;          // GEMM row tiles
    int nb = (N + 1023) / 1024;        // scan blocks

    // dtype probe + CSR build + norms
    k_probe<<<1, 1>>>(ei);
    k_zero_deg<<<gN, T>>>(N);
    k_hist<<<gE, T>>>(ei, E);
    k_scan1<<<nb, 1024>>>(N);
    k_scan2<<<1, 1024>>>(nb);
    k_scan3<<<gN, T>>>(N);
    k_place<<<gE, T>>>(ei, E);

    // layer 1
    k_sgemm1<<<gM, T>>>(x, W1, N);
    k_gather1<<<gW, T>>>(b1, N);

    // layer 2 + head
    k_sgemm2<<<gM, T>>>(x, W2, N);
    k_gather2<<<gW, T>>>(b2, Wout, bout, out, N);
}

// round 6
// speedup vs baseline: 1.2872x; 1.2872x over previous
#include <cuda_runtime.h>
#include <cuda_bf16.h>
#include <cstdint>

// GCN: 2x gcn_conv + concat + leaky_relu + linear head.
// GEMMs: bf16x3 split-precision on mma.sync (HMMA) — tcgen05 unavailable
// because the harness targets plain sm_103 (no 'a' feature set).

#define NMAX 100352
#define EMAX 602112

// ---- static device scratch ----
__device__ __align__(16) float g_h  [(size_t)NMAX * 128];  // GEMM output (h1 then h2)
__device__ __align__(16) float g_agg[(size_t)NMAX * 128];  // lk(agg1 + b1)
__device__ __align__(16) float g_dinv[NMAX];
__device__ __align__(16) int   g_deg [NMAX];
__device__ __align__(16) int   g_rowptr[NMAX];
__device__ __align__(16) int   g_cursor[NMAX];
__device__ __align__(16) int   g_csrc[EMAX];
__device__ __align__(16) int   g_bsum[1024];
__device__ int g_is64;
// pre-split B images, padded [n][k] layout, stride 136 bf16.
// slot 0 = W1, slots 1,2 = W2 top/bottom halves. 128*136 ushorts per slot.
#define BSTRIDE 136
#define BSLOTSZ (128 * BSTRIDE)
__device__ __align__(16) unsigned short g_Bhi[3 * BSLOTSZ];
__device__ __align__(16) unsigned short g_Blo[3 * BSLOTSZ];

__device__ __forceinline__ float lk(float v) { return v > 0.f ? v : 0.01f * v; }

__device__ __forceinline__ int edge_at(const int* ei, int is64, size_t idx) {
    if (is64) return (int)((const long long*)ei)[idx];
    return ei[idx];
}

__device__ __forceinline__ void split2(float a, float b, uint32_t& hi, uint32_t& lo) {
    __nv_bfloat16 ha = __float2bfloat16(a), hb = __float2bfloat16(b);
    __nv_bfloat16 la = __float2bfloat16(a - __bfloat162float(ha));
    __nv_bfloat16 lb = __float2bfloat16(b - __bfloat162float(hb));
    __nv_bfloat162 H = __nv_bfloat162(ha, hb), L = __nv_bfloat162(la, lb);
    hi = *(uint32_t*)&H;  lo = *(uint32_t*)&L;
}

__device__ __forceinline__ void mma16816(float* c, const uint32_t* a, const uint32_t* b) {
    asm volatile(
        "mma.sync.aligned.m16n8k16.row.col.f32.bf16.bf16.f32 "
        "{%0,%1,%2,%3}, {%4,%5,%6,%7}, {%8,%9}, {%0,%1,%2,%3};"
        : "+f"(c[0]), "+f"(c[1]), "+f"(c[2]), "+f"(c[3])
        : "r"(a[0]), "r"(a[1]), "r"(a[2]), "r"(a[3]), "r"(b[0]), "r"(b[1]));
}

// =================== dtype probe + CSR build ===================
__global__ void k_probe(const int* __restrict__ ei) {
    int allz = 1;
    for (int t = 0; t < 64; t++)
        if (ei[2 * t + 1] != 0) { allz = 0; break; }
    g_is64 = allz;
}
__global__ void k_zero_deg(int n) {
    int i = blockIdx.x * blockDim.x + threadIdx.x;
    if (i < n) g_deg[i] = 0;
}
__global__ void k_hist(const int* __restrict__ ei, int E) {
    int e = blockIdx.x * blockDim.x + threadIdx.x;
    if (e < E) atomicAdd(&g_deg[edge_at(ei, g_is64, (size_t)E + e)], 1);
}
__global__ void __launch_bounds__(1024) k_scan1(int n) {
    __shared__ int sh[1024];
    int tid = threadIdx.x;
    int i = blockIdx.x * 1024 + tid;
    int v = (i < n) ? g_deg[i] : 0;
    sh[tid] = v;  __syncthreads();
    for (int o = 1; o < 1024; o <<= 1) {
        int t = (tid >= o) ? sh[tid - o] : 0;
        __syncthreads(); sh[tid] += t; __syncthreads();
    }
    if (i < n) g_rowptr[i] = sh[tid] - v;
    if (tid == 1023) g_bsum[blockIdx.x] = sh[1023];
}
__global__ void __launch_bounds__(1024) k_scan2(int nb) {
    __shared__ int sh[1024];
    int tid = threadIdx.x;
    int v = (tid < nb) ? g_bsum[tid] : 0;
    sh[tid] = v;  __syncthreads();
    for (int o = 1; o < 1024; o <<= 1) {
        int t = (tid >= o) ? sh[tid - o] : 0;
        __syncthreads(); sh[tid] += t; __syncthreads();
    }
    if (tid < nb) g_bsum[tid] = sh[tid] - v;
}
__global__ void k_scan3(int n) {
    int i = blockIdx.x * blockDim.x + threadIdx.x;
    if (i >= n) return;
    int r = g_rowptr[i] + g_bsum[i >> 10];
    g_rowptr[i] = r;  g_cursor[i] = r;
    g_dinv[i] = rsqrtf((float)(g_deg[i] + 1));
}
__global__ void k_place(const int* __restrict__ ei, int E) {
    int e = blockIdx.x * blockDim.x + threadIdx.x;
    if (e >= E) return;
    int is64 = g_is64;
    int s = edge_at(ei, is64, e);
    int d = edge_at(ei, is64, (size_t)E + e);
    g_csrc[atomicAdd(&g_cursor[d], 1)] = s;
}

// =================== W pre-split: B[n][k] = W[k][n], padded stride ===================
__global__ void k_prepB(const float* __restrict__ W, int Krows, int slotBase) {
    int idx = blockIdx.x * blockDim.x + threadIdx.x;
    if (idx >= Krows * 128) return;
    int k = idx >> 7, n = idx & 127;
    int slot = slotBase + (k >> 7);
    int kl = k & 127;
    float v = W[(size_t)k * 128 + n];
    __nv_bfloat16 h = __float2bfloat16(v);
    __nv_bfloat16 l = __float2bfloat16(v - __bfloat162float(h));
    size_t off = (size_t)slot * BSLOTSZ + n * BSTRIDE + kl;
    g_Bhi[off] = *(unsigned short*)&h;
    g_Blo[off] = *(unsigned short*)&l;
}

// =================== tensor-core GEMM (mma.sync bf16x3) ===================
// g_h[M,128] = sum over phases of Aphase[M,128] @ B[slot+phase]
// phase 0: A = A0 (optionally leaky'd), phase 1: A = g_agg.
// acc persists in registers across phases.
#define ASTRIDE 136
#define SM_A_HI 0
#define SM_A_LO (128 * ASTRIDE * 2)
#define SM_B_HI (2 * 128 * ASTRIDE * 2)
#define SM_B_LO (3 * 128 * ASTRIDE * 2)
#define SM_TOTAL (4 * 128 * ASTRIDE * 2)

__global__ void __launch_bounds__(256, 1)
k_tgemm(const float* __restrict__ A0, int lk0, int nphase, int bslot, int M) {
    extern __shared__ char smem[];
    __nv_bfloat16* Ah = (__nv_bfloat16*)(smem + SM_A_HI);
    __nv_bfloat16* Al = (__nv_bfloat16*)(smem + SM_A_LO);
    __nv_bfloat16* Bh = (__nv_bfloat16*)(smem + SM_B_HI);
    __nv_bfloat16* Bl = (__nv_bfloat16*)(smem + SM_B_LO);

    int tid  = threadIdx.x;
    int wid  = tid >> 5;
    int lane = tid & 31;
    int g    = lane >> 2;      // group id 0..7
    int q    = lane & 3;       // thread-in-group
    int wm   = wid & 3;        // warp m index (0..3) -> rows wm*32..wm*32+31
    int wn   = wid >> 2;       // warp n index (0..1) -> cols wn*64..wn*64+63
    int m0   = blockIdx.x * 128;

    float acc[2][8][4];
#pragma unroll
    for (int i = 0; i < 2; i++)
#pragma unroll
        for (int j = 0; j < 8; j++)
#pragma unroll
            for (int c = 0; c < 4; c++) acc[i][j][c] = 0.f;

    for (int phase = 0; phase < nphase; phase++) {
        const float* A = phase ? g_agg : A0;
        int applyLk = phase ? 0 : lk0;

        if (phase) __syncthreads();   // protect SMEM reuse

        // --- load A tile (128x128 fp32), split hi/lo into padded SMEM ---
        for (int t = tid; t < 2048; t += 256) {   // 128 rows x 16 chunks of 8
            int row = t >> 4;
            int kc  = (t & 15) << 3;
            int gr  = m0 + row;
            float4 v0 = make_float4(0.f, 0.f, 0.f, 0.f), v1 = v0;
            if (gr < M) {
                v0 = *(const float4*)(A + (size_t)gr * 128 + kc);
                v1 = *(const float4*)(A + (size_t)gr * 128 + kc + 4);
                if (applyLk) {
                    v0.x = lk(v0.x); v0.y = lk(v0.y); v0.z = lk(v0.z); v0.w = lk(v0.w);
                    v1.x = lk(v1.x); v1.y = lk(v1.y); v1.z = lk(v1.z); v1.w = lk(v1.w);
                }
            }
            uint4 hi4, lo4;
            split2(v0.x, v0.y, hi4.x, lo4.x);
            split2(v0.z, v0.w, hi4.y, lo4.y);
            split2(v1.x, v1.y, hi4.z, lo4.z);
            split2(v1.z, v1.w, hi4.w, lo4.w);
            *(uint4*)(Ah + row * ASTRIDE + kc) = hi4;
            *(uint4*)(Al + row * ASTRIDE + kc) = lo4;
        }
        // --- copy pre-split B slot images ---
        {
            int slot = bslot + phase;
            const uint4* bh = (const uint4*)(g_Bhi + (size_t)slot * BSLOTSZ);
            const uint4* bl = (const uint4*)(g_Blo + (size_t)slot * BSLOTSZ);
            uint4* dh = (uint4*)Bh;
            uint4* dl = (uint4*)Bl;
            for (int t = tid; t < BSLOTSZ / 8; t += 256) { dh[t] = bh[t]; dl[t] = bl[t]; }
        }
        __syncthreads();

        // --- MMA mainloop: 8 K-steps of 16 ---
#pragma unroll
        for (int ks = 0; ks < 8; ks++) {
            int ko = ks * 16;
            uint32_t ahi[2][4], alo[2][4];
#pragma unroll
            for (int mt = 0; mt < 2; mt++) {
                int r = (wm * 32 + mt * 16 + g) * ASTRIDE + ko + q * 2;
                ahi[mt][0] = *(uint32_t*)(Ah + r);
                ahi[mt][1] = *(uint32_t*)(Ah + r + 8 * ASTRIDE);
                ahi[mt][2] = *(uint32_t*)(Ah + r + 8);
                ahi[mt][3] = *(uint32_t*)(Ah + r + 8 * ASTRIDE + 8);
                alo[mt][0] = *(uint32_t*)(Al + r);
                alo[mt][1] = *(uint32_t*)(Al + r + 8 * ASTRIDE);
                alo[mt][2] = *(uint32_t*)(Al + r + 8);
                alo[mt][3] = *(uint32_t*)(Al + r + 8 * ASTRIDE + 8);
            }
#pragma unroll
            for (int nt = 0; nt < 8; nt++) {
                int rb = (wn * 64 + nt * 8 + g) * BSTRIDE + ko + q * 2;
                uint32_t bhi[2], blo[2];
                bhi[0] = *(uint32_t*)(Bh + rb);
                bhi[1] = *(uint32_t*)(Bh + rb + 8);
                blo[0] = *(uint32_t*)(Bl + rb);
                blo[1] = *(uint32_t*)(Bl + rb + 8);
#pragma unroll
                for (int mt = 0; mt < 2; mt++) {
                    mma16816(acc[mt][nt], ahi[mt], bhi);   // hi*hi
                    mma16816(acc[mt][nt], ahi[mt], blo);   // hi*lo
                    mma16816(acc[mt][nt], alo[mt], bhi);   // lo*hi
                }
            }
        }
    }

    // --- epilogue: write fp32 rows ---
#pragma unroll
    for (int mt = 0; mt < 2; mt++) {
        int r0 = m0 + wm * 32 + mt * 16 + g;
#pragma unroll
        for (int nt = 0; nt < 8; nt++) {
            int cc = wn * 64 + nt * 8 + q * 2;
            if (r0 < M)
                *(float2*)(g_h + (size_t)r0 * 128 + cc) =
                    make_float2(acc[mt][nt][0], acc[mt][nt][1]);
            if (r0 + 8 < M)
                *(float2*)(g_h + (size_t)(r0 + 8) * 128 + cc) =
                    make_float2(acc[mt][nt][2], acc[mt][nt][3]);
        }
    }
}

// =================== aggregation ===================
__global__ void k_gather1(const float* __restrict__ b1, int N) {
    int node = (blockIdx.x * blockDim.x + threadIdx.x) >> 5;
    int lane = threadIdx.x & 31;
    if (node >= N) return;
    int c4 = lane << 2;
    float di = g_dinv[node];
    float4 acc = *(const float4*)(g_h + (size_t)node * 128 + c4);
    float s = di * di;
    acc.x *= s; acc.y *= s; acc.z *= s; acc.w *= s;
    int start = g_rowptr[node], deg = g_deg[node];
    for (int j = 0; j < deg; j++) {
        int src = g_csrc[start + j];
        float nrm = di * g_dinv[src];
        float4 v = *(const float4*)(g_h + (size_t)src * 128 + c4);
        acc.x = fmaf(v.x, nrm, acc.x); acc.y = fmaf(v.y, nrm, acc.y);
        acc.z = fmaf(v.z, nrm, acc.z); acc.w = fmaf(v.w, nrm, acc.w);
    }
    float4 bb = *(const float4*)(b1 + c4);
    acc.x = lk(acc.x + bb.x); acc.y = lk(acc.y + bb.y);
    acc.z = lk(acc.z + bb.z); acc.w = lk(acc.w + bb.w);
    *(float4*)(g_agg + (size_t)node * 128 + c4) = acc;
}

__global__ void k_gather2(const float* __restrict__ b2, const float* __restrict__ Wout,
                          const float* __restrict__ bout, float* __restrict__ out, int N) {
    int node = (blockIdx.x * blockDim.x + threadIdx.x) >> 5;
    int lane = threadIdx.x & 31;
    if (node >= N) return;
    int c4 = lane << 2;
    float di = g_dinv[node];
    float4 acc = *(const float4*)(g_h + (size_t)node * 128 + c4);
    float s = di * di;
    acc.x *= s; acc.y *= s; acc.z *= s; acc.w *= s;
    int start = g_rowptr[node], deg = g_deg[node];
    for (int j = 0; j < deg; j++) {
        int src = g_csrc[start + j];
        float nrm = di * g_dinv[src];
        float4 v = *(const float4*)(g_h + (size_t)src * 128 + c4);
        acc.x = fmaf(v.x, nrm, acc.x); acc.y = fmaf(v.y, nrm, acc.y);
        acc.z = fmaf(v.z, nrm, acc.z); acc.w = fmaf(v.w, nrm, acc.w);
    }
    float4 bb = *(const float4*)(b2 + c4);
    float4 ww = *(const float4*)(Wout + c4);
    float r = lk(acc.x + bb.x) * ww.x + lk(acc.y + bb.y) * ww.y +
              lk(acc.z + bb.z) * ww.z + lk(acc.w + bb.w) * ww.w;
#pragma unroll
    for (int o = 16; o; o >>= 1) r += __shfl_xor_sync(0xFFFFFFFFu, r, o);
    if (lane == 0) out[node] = r + bout[0];
}

// =================== launch ===================
extern "C" void kernel_launch(void* const* d_in, const int* in_sizes, int n_in,
                              void* d_out, int out_size) {
    const float* x    = (const float*)d_in[0];
    const int*   ei   = (const int*)d_in[1];
    const float* W1   = (const float*)d_in[2];
    const float* b1   = (const float*)d_in[3];
    const float* W2   = (const float*)d_in[4];
    const float* b2   = (const float*)d_in[5];
    const float* Wout = (const float*)d_in[6];
    const float* bout = (const float*)d_in[7];
    float*       out  = (float*)d_out;

    int N = in_sizes[0] / 128;
    int E = in_sizes[1] / 2;

    cudaFuncSetAttribute(k_tgemm, cudaFuncAttributeMaxDynamicSharedMemorySize, SM_TOTAL);

    const int T = 256;
    int gN = (N + T - 1) / T;
    int gE = (E + T - 1) / T;
    int gW = (N * 32 + T - 1) / T;
    int gM = (N + 127) / 128;
    int nb = (N + 1023) / 1024;

    // dtype probe + CSR build + norms
    k_probe<<<1, 1>>>(ei);
    k_zero_deg<<<gN, T>>>(N);
    k_hist<<<gE, T>>>(ei, E);
    k_scan1<<<nb, 1024>>>(N);
    k_scan2<<<1, 1024>>>(nb);
    k_scan3<<<gN, T>>>(N);
    k_place<<<gE, T>>>(ei, E);

    // weight pre-split (tiny)
    k_prepB<<<(128 * 128 + T - 1) / T, T>>>(W1, 128, 0);
    k_prepB<<<(256 * 128 + T - 1) / T, T>>>(W2, 256, 1);

    // layer 1: h1 = x @ W1
    k_tgemm<<<gM, T, SM_TOTAL>>>(x, 0, 1, 0, N);
    k_gather1<<<gW, T>>>(b1, N);

    // layer 2: h2 = lk(x) @ W2_top + agg1 @ W2_bot  (register-accumulated phases)
    k_tgemm<<<gM, T, SM_TOTAL>>>(x, 1, 2, 1, N);
    k_gather2<<<gW, T>>>(b2, Wout, bout, out, N);
}

// round 7
// speedup vs baseline: 1.3204x; 1.0258x over previous
#include <cuda_runtime.h>
#include <cuda_bf16.h>
#include <cstdint>

// GCN: 2x gcn_conv + concat + leaky_relu + linear head.
// GEMMs: bf16x3 split-precision on mma.sync (HMMA) + ldmatrix fragment loads.

#define NMAX 100352
#define EMAX 602112

// ---- static device scratch ----
__device__ __align__(16) float g_h  [(size_t)NMAX * 128];  // GEMM output (h1 then h2)
__device__ __align__(16) float g_agg[(size_t)NMAX * 128];  // lk(agg1 + b1)
__device__ __align__(16) float g_dinv[NMAX];
__device__ __align__(16) int   g_deg [NMAX];
__device__ __align__(16) int   g_rowptr[NMAX];
__device__ __align__(16) int   g_cursor[NMAX];
__device__ __align__(16) int   g_csrc[EMAX];
__device__ __align__(16) int   g_bsum[1024];
__device__ int g_is64;
// pre-split B images, padded [n][k] layout, stride 136 bf16 (272 B).
#define BSTRIDE 136
#define BSLOTSZ (128 * BSTRIDE)
__device__ __align__(16) unsigned short g_Bhi[3 * BSLOTSZ];
__device__ __align__(16) unsigned short g_Blo[3 * BSLOTSZ];

__device__ __forceinline__ float lk(float v) { return v > 0.f ? v : 0.01f * v; }

__device__ __forceinline__ int edge_at(const int* ei, int is64, size_t idx) {
    if (is64) return (int)((const long long*)ei)[idx];
    return ei[idx];
}

__device__ __forceinline__ void split2(float a, float b, uint32_t& hi, uint32_t& lo) {
    __nv_bfloat16 ha = __float2bfloat16(a), hb = __float2bfloat16(b);
    __nv_bfloat16 la = __float2bfloat16(a - __bfloat162float(ha));
    __nv_bfloat16 lb = __float2bfloat16(b - __bfloat162float(hb));
    __nv_bfloat162 H = __nv_bfloat162(ha, hb), L = __nv_bfloat162(la, lb);
    hi = *(uint32_t*)&H;  lo = *(uint32_t*)&L;
}

__device__ __forceinline__ void mma16816(float* c, const uint32_t* a, const uint32_t* b) {
    asm volatile(
        "mma.sync.aligned.m16n8k16.row.col.f32.bf16.bf16.f32 "
        "{%0,%1,%2,%3}, {%4,%5,%6,%7}, {%8,%9}, {%0,%1,%2,%3};"
        : "+f"(c[0]), "+f"(c[1]), "+f"(c[2]), "+f"(c[3])
        : "r"(a[0]), "r"(a[1]), "r"(a[2]), "r"(a[3]), "r"(b[0]), "r"(b[1]));
}

__device__ __forceinline__ uint32_t smem_u32(const void* p) {
    uint32_t a;
    asm("{ .reg .u64 t; cvta.to.shared.u64 t, %1; cvt.u32.u64 %0, t; }" : "=r"(a) : "l"(p));
    return a;
}

#define LDSM_X4(R, addr) \
    asm volatile("ldmatrix.sync.aligned.m8n8.x4.shared.b16 {%0,%1,%2,%3}, [%4];" \
        : "=r"((R)[0]), "=r"((R)[1]), "=r"((R)[2]), "=r"((R)[3]) : "r"(addr))

// =================== CSR build (probe folded into zero_deg) ===================
__global__ void k_zero_deg(const int* __restrict__ ei, int n) {
    int i = blockIdx.x * blockDim.x + threadIdx.x;
    if (i < n) g_deg[i] = 0;
    if (blockIdx.x == 0 && threadIdx.x == 0) {
        int allz = 1;
        for (int t = 0; t < 64; t++)
            if (ei[2 * t + 1] != 0) { allz = 0; break; }
        g_is64 = allz;
    }
}
__global__ void k_hist(const int* __restrict__ ei, int E) {
    int e = blockIdx.x * blockDim.x + threadIdx.x;
    if (e < E) atomicAdd(&g_deg[edge_at(ei, g_is64, (size_t)E + e)], 1);
}
__global__ void __launch_bounds__(1024) k_scan1(int n) {
    __shared__ int sh[1024];
    int tid = threadIdx.x;
    int i = blockIdx.x * 1024 + tid;
    int v = (i < n) ? g_deg[i] : 0;
    sh[tid] = v;  __syncthreads();
    for (int o = 1; o < 1024; o <<= 1) {
        int t = (tid >= o) ? sh[tid - o] : 0;
        __syncthreads(); sh[tid] += t; __syncthreads();
    }
    if (i < n) g_rowptr[i] = sh[tid] - v;
    if (tid == 1023) g_bsum[blockIdx.x] = sh[1023];
}
__global__ void __launch_bounds__(1024) k_scan2(int nb) {
    __shared__ int sh[1024];
    int tid = threadIdx.x;
    int v = (tid < nb) ? g_bsum[tid] : 0;
    sh[tid] = v;  __syncthreads();
    for (int o = 1; o < 1024; o <<= 1) {
        int t = (tid >= o) ? sh[tid - o] : 0;
        __syncthreads(); sh[tid] += t; __syncthreads();
    }
    if (tid < nb) g_bsum[tid] = sh[tid] - v;
}
__global__ void k_scan3(int n) {
    int i = blockIdx.x * blockDim.x + threadIdx.x;
    if (i >= n) return;
    int r = g_rowptr[i] + g_bsum[i >> 10];
    g_rowptr[i] = r;  g_cursor[i] = r;
    g_dinv[i] = rsqrtf((float)(g_deg[i] + 1));
}
__global__ void k_place(const int* __restrict__ ei, int E) {
    int e = blockIdx.x * blockDim.x + threadIdx.x;
    if (e >= E) return;
    int is64 = g_is64;
    int s = edge_at(ei, is64, e);
    int d = edge_at(ei, is64, (size_t)E + e);
    g_csrc[atomicAdd(&g_cursor[d], 1)] = s;
}

// =================== W pre-split: B[n][k] = W[k][n], padded stride ===================
__global__ void k_prepB(const float* __restrict__ W, int Krows, int slotBase) {
    int idx = blockIdx.x * blockDim.x + threadIdx.x;
    if (idx >= Krows * 128) return;
    int k = idx >> 7, n = idx & 127;
    int slot = slotBase + (k >> 7);
    int kl = k & 127;
    float v = W[(size_t)k * 128 + n];
    __nv_bfloat16 h = __float2bfloat16(v);
    __nv_bfloat16 l = __float2bfloat16(v - __bfloat162float(h));
    size_t off = (size_t)slot * BSLOTSZ + n * BSTRIDE + kl;
    g_Bhi[off] = *(unsigned short*)&h;
    g_Blo[off] = *(unsigned short*)&l;
}

// =================== tensor-core GEMM (mma.sync bf16x3 + ldmatrix) ===================
#define ASTRIDE 136
#define ROWB (ASTRIDE * 2)                 // 272 bytes per row
#define SM_A_HI 0
#define SM_A_LO (128 * ROWB)
#define SM_B_HI (2 * 128 * ROWB)
#define SM_B_LO (3 * 128 * ROWB)
#define SM_TOTAL (4 * 128 * ROWB)

__global__ void __launch_bounds__(256, 1)
k_tgemm(const float* __restrict__ A0, int lk0, int nphase, int bslot, int M) {
    extern __shared__ char smem[];
    __nv_bfloat16* Ah = (__nv_bfloat16*)(smem + SM_A_HI);
    __nv_bfloat16* Al = (__nv_bfloat16*)(smem + SM_A_LO);
    uint32_t smBase = smem_u32(smem);

    int tid  = threadIdx.x;
    int wid  = tid >> 5;
    int lane = tid & 31;
    int q    = lane & 3;
    int wm   = wid & 3;        // rows wm*32..+31
    int wn   = wid >> 2;       // cols wn*64..+63
    int m0   = blockIdx.x * 128;

    // ldmatrix lane-address components (constant per thread)
    int aRow  = (lane & 15);            // + mbase
    int aColX = (lane >> 4) << 4;       // 0 or 16 bytes (k halves)
    int bRow  = (lane & 7) + ((lane >> 4) << 3);   // 0..15 within nt-pair
    int bColX = ((lane >> 3) & 1) << 4;            // 0 or 16 bytes

    float acc[2][8][4];
#pragma unroll
    for (int i = 0; i < 2; i++)
#pragma unroll
        for (int j = 0; j < 8; j++)
#pragma unroll
            for (int c = 0; c < 4; c++) acc[i][j][c] = 0.f;

    for (int phase = 0; phase < nphase; phase++) {
        const float* A = phase ? g_agg : A0;
        int applyLk = phase ? 0 : lk0;

        if (phase) __syncthreads();   // protect SMEM reuse

        // --- load A tile (128x128 fp32), split hi/lo into padded SMEM ---
        for (int t = tid; t < 2048; t += 256) {
            int row = t >> 4;
            int kc  = (t & 15) << 3;
            int gr  = m0 + row;
            float4 v0 = make_float4(0.f, 0.f, 0.f, 0.f), v1 = v0;
            if (gr < M) {
                v0 = *(const float4*)(A + (size_t)gr * 128 + kc);
                v1 = *(const float4*)(A + (size_t)gr * 128 + kc + 4);
                if (applyLk) {
                    v0.x = lk(v0.x); v0.y = lk(v0.y); v0.z = lk(v0.z); v0.w = lk(v0.w);
                    v1.x = lk(v1.x); v1.y = lk(v1.y); v1.z = lk(v1.z); v1.w = lk(v1.w);
                }
            }
            uint4 hi4, lo4;
            split2(v0.x, v0.y, hi4.x, lo4.x);
            split2(v0.z, v0.w, hi4.y, lo4.y);
            split2(v1.x, v1.y, hi4.z, lo4.z);
            split2(v1.z, v1.w, hi4.w, lo4.w);
            *(uint4*)(Ah + row * ASTRIDE + kc) = hi4;
            *(uint4*)(Al + row * ASTRIDE + kc) = lo4;
        }
        // --- copy pre-split B slot images ---
        {
            int slot = bslot + phase;
            const uint4* bh = (const uint4*)(g_Bhi + (size_t)slot * BSLOTSZ);
            const uint4* bl = (const uint4*)(g_Blo + (size_t)slot * BSLOTSZ);
            uint4* dh = (uint4*)(smem + SM_B_HI);
            uint4* dl = (uint4*)(smem + SM_B_LO);
            for (int t = tid; t < BSLOTSZ / 8; t += 256) { dh[t] = bh[t]; dl[t] = bl[t]; }
        }
        __syncthreads();

        // --- MMA mainloop: 8 K-steps of 16, ldmatrix fragment loads ---
#pragma unroll
        for (int ks = 0; ks < 8; ks++) {
            int kb = ks * 32;      // byte offset of this k-step within a row

            uint32_t ahi[2][4], alo[2][4];
#pragma unroll
            for (int mt = 0; mt < 2; mt++) {
                uint32_t ad = smBase + (uint32_t)(wm * 32 + mt * 16 + aRow) * ROWB
                            + kb + aColX;
                LDSM_X4(ahi[mt], ad + SM_A_HI);
                LDSM_X4(alo[mt], ad + SM_A_LO);
            }

            uint32_t bhi[8][2], blo[8][2];
#pragma unroll
            for (int t = 0; t < 4; t++) {      // nt pair (2t, 2t+1)
                uint32_t bd = smBase + (uint32_t)(wn * 64 + t * 16 + bRow) * ROWB
                            + kb + bColX;
                uint32_t r[4];
                LDSM_X4(r, bd + SM_B_HI);
                bhi[2 * t][0] = r[0]; bhi[2 * t][1] = r[1];
                bhi[2 * t + 1][0] = r[2]; bhi[2 * t + 1][1] = r[3];
                LDSM_X4(r, bd + SM_B_LO);
                blo[2 * t][0] = r[0]; blo[2 * t][1] = r[1];
                blo[2 * t + 1][0] = r[2]; blo[2 * t + 1][1] = r[3];
            }

#pragma unroll
            for (int nt = 0; nt < 8; nt++)
#pragma unroll
                for (int mt = 0; mt < 2; mt++) {
                    mma16816(acc[mt][nt], ahi[mt], bhi[nt]);   // hi*hi
                    mma16816(acc[mt][nt], ahi[mt], blo[nt]);   // hi*lo
                    mma16816(acc[mt][nt], alo[mt], bhi[nt]);   // lo*hi
                }
        }
    }

    // --- epilogue ---
    int g = lane >> 2;
#pragma unroll
    for (int mt = 0; mt < 2; mt++) {
        int r0 = m0 + wm * 32 + mt * 16 + g;
#pragma unroll
        for (int nt = 0; nt < 8; nt++) {
            int cc = wn * 64 + nt * 8 + q * 2;
            if (r0 < M)
                *(float2*)(g_h + (size_t)r0 * 128 + cc) =
                    make_float2(acc[mt][nt][0], acc[mt][nt][1]);
            if (r0 + 8 < M)
                *(float2*)(g_h + (size_t)(r0 + 8) * 128 + cc) =
                    make_float2(acc[mt][nt][2], acc[mt][nt][3]);
        }
    }
}

// =================== aggregation ===================
__global__ void k_gather1(const float* __restrict__ b1, int N) {
    int node = (blockIdx.x * blockDim.x + threadIdx.x) >> 5;
    int lane = threadIdx.x & 31;
    if (node >= N) return;
    int c4 = lane << 2;
    float di = g_dinv[node];
    float4 acc = *(const float4*)(g_h + (size_t)node * 128 + c4);
    float s = di * di;
    acc.x *= s; acc.y *= s; acc.z *= s; acc.w *= s;
    int start = g_rowptr[node], deg = g_deg[node];
    for (int j = 0; j < deg; j++) {
        int src = g_csrc[start + j];
        float nrm = di * g_dinv[src];
        float4 v = *(const float4*)(g_h + (size_t)src * 128 + c4);
        acc.x = fmaf(v.x, nrm, acc.x); acc.y = fmaf(v.y, nrm, acc.y);
        acc.z = fmaf(v.z, nrm, acc.z); acc.w = fmaf(v.w, nrm, acc.w);
    }
    float4 bb = *(const float4*)(b1 + c4);
    acc.x = lk(acc.x + bb.x); acc.y = lk(acc.y + bb.y);
    acc.z = lk(acc.z + bb.z); acc.w = lk(acc.w + bb.w);
    *(float4*)(g_agg + (size_t)node * 128 + c4) = acc;
}

__global__ void k_gather2(const float* __restrict__ b2, const float* __restrict__ Wout,
                          const float* __restrict__ bout, float* __restrict__ out, int N) {
    int node = (blockIdx.x * blockDim.x + threadIdx.x) >> 5;
    int lane = threadIdx.x & 31;
    if (node >= N) return;
    int c4 = lane << 2;
    float di = g_dinv[node];
    float4 acc = *(const float4*)(g_h + (size_t)node * 128 + c4);
    float s = di * di;
    acc.x *= s; acc.y *= s; acc.z *= s; acc.w *= s;
    int start = g_rowptr[node], deg = g_deg[node];
    for (int j = 0; j < deg; j++) {
        int src = g_csrc[start + j];
        float nrm = di * g_dinv[src];
        float4 v = *(const float4*)(g_h + (size_t)src * 128 + c4);
        acc.x = fmaf(v.x, nrm, acc.x); acc.y = fmaf(v.y, nrm, acc.y);
        acc.z = fmaf(v.z, nrm, acc.z); acc.w = fmaf(v.w, nrm, acc.w);
    }
    float4 bb = *(const float4*)(b2 + c4);
    float4 ww = *(const float4*)(Wout + c4);
    float r = lk(acc.x + bb.x) * ww.x + lk(acc.y + bb.y) * ww.y +
              lk(acc.z + bb.z) * ww.z + lk(acc.w + bb.w) * ww.w;
#pragma unroll
    for (int o = 16; o; o >>= 1) r += __shfl_xor_sync(0xFFFFFFFFu, r, o);
    if (lane == 0) out[node] = r + bout[0];
}

// =================== launch ===================
extern "C" void kernel_launch(void* const* d_in, const int* in_sizes, int n_in,
                              void* d_out, int out_size) {
    const float* x    = (const float*)d_in[0];
    const int*   ei   = (const int*)d_in[1];
    const float* W1   = (const float*)d_in[2];
    const float* b1   = (const float*)d_in[3];
    const float* W2   = (const float*)d_in[4];
    const float* b2   = (const float*)d_in[5];
    const float* Wout = (const float*)d_in[6];
    const float* bout = (const float*)d_in[7];
    float*       out  = (float*)d_out;

    int N = in_sizes[0] / 128;
    int E = in_sizes[1] / 2;

    cudaFuncSetAttribute(k_tgemm, cudaFuncAttributeMaxDynamicSharedMemorySize, SM_TOTAL);

    const int T = 256;
    int gN = (N + T - 1) / T;
    int gE = (E + T - 1) / T;
    int gW = (N * 32 + T - 1) / T;
    int gM = (N + 127) / 128;
    int nb = (N + 1023) / 1024;

    // CSR build + norms (probe folded into zero_deg)
    k_zero_deg<<<gN, T>>>(ei, N);
    k_hist<<<gE, T>>>(ei, E);
    k_scan1<<<nb, 1024>>>(N);
    k_scan2<<<1, 1024>>>(nb);
    k_scan3<<<gN, T>>>(N);
    k_place<<<gE, T>>>(ei, E);

    // weight pre-split (tiny)
    k_prepB<<<(128 * 128 + T - 1) / T, T>>>(W1, 128, 0);
    k_prepB<<<(256 * 128 + T - 1) / T, T>>>(W2, 256, 1);

    // layer 1: h1 = x @ W1
    k_tgemm<<<gM, T, SM_TOTAL>>>(x, 0, 1, 0, N);
    k_gather1<<<gW, T>>>(b1, N);

    // layer 2: h2 = lk(x) @ W2_top + agg1 @ W2_bot  (register-accumulated phases)
    k_tgemm<<<gM, T, SM_TOTAL>>>(x, 1, 2, 1, N);
    k_gather2<<<gW, T>>>(b2, Wout, bout, out, N);
}